// round 1
// baseline (speedup 1.0000x reference)
#include <cuda_runtime.h>
#include <math.h>
#include <stdint.h>

// Problem dims
#define BB 32
#define TT 256
#define CC 64
#define HH 64

// Output layout (floats)
#define LOGITS_OFF 0
#define DNC_OFF    64
#define MIX_OFF    131136ull              // 64 + 32*4096
#define RL_OFF     33685568ull            // MIX_OFF + 32*256*4096

// ---------------- scratch (static device memory; no allocs) ----------------
__device__ float g_h1[8192u * 2048u];     // 64 MB
__device__ float g_h2[8192u * 1024u];     // 32 MB
__device__ float g_rl[BB];

// ---------------- shared mem layout for recurrent kernel (floats) ----------
#define OFF_WHHT 0          /* [64][192] w_hh transposed: whhT[h*192+j] = w_hh[j*64+h] */
#define OFF_QWT  12288      /* [64][64]  qwT[h*64+j]=q_w[j*64+h] */
#define OFF_KWT  16384
#define OFF_GATE 20480      /* [64][64] gate_b */
#define OFF_H    24576      /* [64][65] */
#define OFF_HN   28736
#define OFF_Q    32896
#define OFF_K    37056
#define OFF_TR   41216
#define OFF_DNC  45376      /* [64][64] */
#define OFF_XT   49472      /* [64] */
#define OFF_A    49536      /* [192] */
#define OFF_B0   49728      /* [192] */
#define OFF_BHH  49920      /* [192] */
#define OFF_QB   50112      /* [64] */
#define OFF_KB   50176
#define OFF_PW   50240
#define OFF_RED  50304      /* [64] */
#define SMEM_FLOATS 50368
#define SMEM_BYTES  (SMEM_FLOATS * 4)

__device__ __forceinline__ float sigf(float x) { return 1.f / (1.f + __expf(-x)); }

// ============================================================================
// Recurrent kernel: one CTA per batch, persistent over all T steps.
// ============================================================================
__global__ __launch_bounds__(256) void recurrent_kernel(
    const float* __restrict__ x,
    const float* __restrict__ emb_w, const float* __restrict__ emb_b,
    const float* __restrict__ w_ih, const float* __restrict__ w_hh,
    const float* __restrict__ b_ih, const float* __restrict__ b_hh,
    const float* __restrict__ q_w, const float* __restrict__ q_b,
    const float* __restrict__ k_w, const float* __restrict__ k_b,
    const float* __restrict__ gate_b,
    const float* __restrict__ pred_w, const float* __restrict__ pred_b,
    float* __restrict__ out)
{
    extern __shared__ float s[];
    const int b = blockIdx.x;
    const int tid = threadIdx.x;
    const int tx = tid & 15, ty = tid >> 4;
    const int c0 = ty * 4, j0 = tx * 4;

    // ---- load weights / precompute folded input projection ----
    for (int i = tid; i < 12288; i += 256) {        // whhT
        int j = i / 64, h = i % 64;
        s[OFF_WHHT + h * 192 + j] = w_hh[i];
    }
    for (int i = tid; i < 4096; i += 256) {
        int j = i / 64, h = i % 64;
        s[OFF_QWT + h * 64 + j] = q_w[i];
        s[OFF_KWT + h * 64 + j] = k_w[i];
        s[OFF_GATE + i] = gate_b[i];
    }
    if (tid < 192) {
        float a = 0.f, b0v = 0.f;
        #pragma unroll
        for (int e = 0; e < 32; e++) {
            float w = w_ih[tid * 32 + e];
            a += w * emb_w[e];
            b0v += w * emb_b[e];
        }
        s[OFF_A + tid] = a;
        s[OFF_B0 + tid] = b0v + b_ih[tid];
        s[OFF_BHH + tid] = b_hh[tid];
    }
    if (tid < 64) {
        s[OFF_QB + tid] = q_b[tid];
        s[OFF_KB + tid] = k_b[tid];
        s[OFF_PW + tid] = pred_w[tid];
    }
    for (int i = tid; i < 4160; i += 256) s[OFF_H + i] = 0.f;   // h0 = 0
    for (int i = tid; i < 4096; i += 256) s[OFF_DNC + i] = 0.f;
    const float pb = pred_b[0];
    float errsum = 0.f;
    __syncthreads();

    for (int t = 0; t < TT; t++) {
        if (tid < 64) s[OFF_XT + tid] = x[((size_t)b * TT + t) * CC + tid];
        __syncthreads();

        // ---- GRU hidden GEMM: gh = h @ w_hh^T (+ b_hh), fused gates ----
        float ar[16], az[16], an_[16];
        #pragma unroll
        for (int ji = 0; ji < 4; ji++) {
            float br = s[OFF_BHH + j0 + ji];
            float bz = s[OFF_BHH + 64 + j0 + ji];
            float bn = s[OFF_BHH + 128 + j0 + ji];
            #pragma unroll
            for (int ci = 0; ci < 4; ci++) { ar[ci*4+ji]=br; az[ci*4+ji]=bz; an_[ci*4+ji]=bn; }
        }
        #pragma unroll 4
        for (int h = 0; h < 64; h++) {
            float hv[4];
            #pragma unroll
            for (int ci = 0; ci < 4; ci++) hv[ci] = s[OFF_H + (c0 + ci) * 65 + h];
            float4 wr4 = *(const float4*)&s[OFF_WHHT + h * 192 + j0];
            float4 wz4 = *(const float4*)&s[OFF_WHHT + h * 192 + 64 + j0];
            float4 wn4 = *(const float4*)&s[OFF_WHHT + h * 192 + 128 + j0];
            float wr[4] = {wr4.x, wr4.y, wr4.z, wr4.w};
            float wz[4] = {wz4.x, wz4.y, wz4.z, wz4.w};
            float wn[4] = {wn4.x, wn4.y, wn4.z, wn4.w};
            #pragma unroll
            for (int ci = 0; ci < 4; ci++)
                #pragma unroll
                for (int ji = 0; ji < 4; ji++) {
                    ar[ci*4+ji]  = fmaf(hv[ci], wr[ji], ar[ci*4+ji]);
                    az[ci*4+ji]  = fmaf(hv[ci], wz[ji], az[ci*4+ji]);
                    an_[ci*4+ji] = fmaf(hv[ci], wn[ji], an_[ci*4+ji]);
                }
        }
        // gates + h_new
        #pragma unroll
        for (int ci = 0; ci < 4; ci++) {
            int c = c0 + ci;
            float xv = s[OFF_XT + c];
            #pragma unroll
            for (int ji = 0; ji < 4; ji++) {
                int j = j0 + ji;
                float gir = fmaf(xv, s[OFF_A + j],        s[OFF_B0 + j]);
                float giz = fmaf(xv, s[OFF_A + 64 + j],   s[OFF_B0 + 64 + j]);
                float gin = fmaf(xv, s[OFF_A + 128 + j],  s[OFF_B0 + 128 + j]);
                float r = sigf(gir + ar[ci*4+ji]);
                float z = sigf(giz + az[ci*4+ji]);
                float n = tanhf(fmaf(r, an_[ci*4+ji], gin));
                s[OFF_HN + c * 65 + j] = (1.f - z) * n + z * s[OFF_H + c * 65 + j];
            }
        }
        __syncthreads();

        // ---- q = hn @ q_w^T + q_b ; k = hn @ k_w^T + k_b ----
        float aq[16], ak[16];
        #pragma unroll
        for (int ji = 0; ji < 4; ji++) {
            float qb = s[OFF_QB + j0 + ji], kb = s[OFF_KB + j0 + ji];
            #pragma unroll
            for (int ci = 0; ci < 4; ci++) { aq[ci*4+ji]=qb; ak[ci*4+ji]=kb; }
        }
        #pragma unroll 4
        for (int h = 0; h < 64; h++) {
            float hv[4];
            #pragma unroll
            for (int ci = 0; ci < 4; ci++) hv[ci] = s[OFF_HN + (c0 + ci) * 65 + h];
            float4 qw4 = *(const float4*)&s[OFF_QWT + h * 64 + j0];
            float4 kw4 = *(const float4*)&s[OFF_KWT + h * 64 + j0];
            float qw[4] = {qw4.x, qw4.y, qw4.z, qw4.w};
            float kw[4] = {kw4.x, kw4.y, kw4.z, kw4.w};
            #pragma unroll
            for (int ci = 0; ci < 4; ci++)
                #pragma unroll
                for (int ji = 0; ji < 4; ji++) {
                    aq[ci*4+ji] = fmaf(hv[ci], qw[ji], aq[ci*4+ji]);
                    ak[ci*4+ji] = fmaf(hv[ci], kw[ji], ak[ci*4+ji]);
                }
        }
        #pragma unroll
        for (int ci = 0; ci < 4; ci++)
            #pragma unroll
            for (int ji = 0; ji < 4; ji++) {
                s[OFF_Q + (c0 + ci) * 65 + j0 + ji] = aq[ci*4+ji];
                s[OFF_K + (c0 + ci) * 65 + j0 + ji] = ak[ci*4+ji];
            }
        __syncthreads();

        // ---- transfer = q @ k^T ----
        float at[16];
        #pragma unroll
        for (int i = 0; i < 16; i++) at[i] = 0.f;
        #pragma unroll 4
        for (int h = 0; h < 64; h++) {
            float qv[4], kv[4];
            #pragma unroll
            for (int ci = 0; ci < 4; ci++) qv[ci] = s[OFF_Q + (c0 + ci) * 65 + h];
            #pragma unroll
            for (int ji = 0; ji < 4; ji++) kv[ji] = s[OFF_K + (j0 + ji) * 65 + h];
            #pragma unroll
            for (int ci = 0; ci < 4; ci++)
                #pragma unroll
                for (int ji = 0; ji < 4; ji++)
                    at[ci*4+ji] = fmaf(qv[ci], kv[ji], at[ci*4+ji]);
        }
        // Frobenius norm reduction
        float ssq = 0.f;
        #pragma unroll
        for (int i = 0; i < 16; i++) ssq = fmaf(at[i], at[i], ssq);
        #pragma unroll
        for (int o = 16; o > 0; o >>= 1) ssq += __shfl_xor_sync(0xffffffffu, ssq, o);
        if ((tid & 31) == 0) s[OFF_RED + (tid >> 5)] = ssq;
        __syncthreads();
        float tot = 0.f;
        #pragma unroll
        for (int w = 0; w < 8; w++) tot += s[OFF_RED + w];
        float rn = 1.f / sqrtf(tot);

        // normalize, tanh, gate; store to smem + gmem mixing + DNC accum
        size_t mixbase = MIX_OFF + ((size_t)(b * TT + t)) * 4096;
        #pragma unroll
        for (int ci = 0; ci < 4; ci++) {
            int c = c0 + ci;
            float tvv[4];
            #pragma unroll
            for (int ji = 0; ji < 4; ji++) {
                int d = j0 + ji;
                float tv = at[ci*4+ji] * rn;
                tv = tanhf(tv);
                float g = sigf(fabsf(tv) + s[OFF_GATE + c * 64 + d]);
                tv *= g;
                s[OFF_TR + c * 65 + d] = tv;
                s[OFF_DNC + c * 64 + d] += tv;
                tvv[ji] = tv;
            }
            float4 v; v.x = tvv[0]; v.y = tvv[1]; v.z = tvv[2]; v.w = tvv[3];
            *(float4*)&out[mixbase + (size_t)c * 64 + j0] = v;
        }
        __syncthreads();

        // ---- h_next = transfer @ h_new ----
        float ah[16];
        #pragma unroll
        for (int i = 0; i < 16; i++) ah[i] = 0.f;
        #pragma unroll 4
        for (int d = 0; d < 64; d++) {
            float tv[4], hv[4];
            #pragma unroll
            for (int ci = 0; ci < 4; ci++) tv[ci] = s[OFF_TR + (c0 + ci) * 65 + d];
            #pragma unroll
            for (int ji = 0; ji < 4; ji++) hv[ji] = s[OFF_HN + d * 65 + j0 + ji];
            #pragma unroll
            for (int ci = 0; ci < 4; ci++)
                #pragma unroll
                for (int ji = 0; ji < 4; ji++)
                    ah[ci*4+ji] = fmaf(tv[ci], hv[ji], ah[ci*4+ji]);
        }
        #pragma unroll
        for (int ci = 0; ci < 4; ci++)
            #pragma unroll
            for (int ji = 0; ji < 4; ji++)
                s[OFF_H + (c0 + ci) * 65 + j0 + ji] = ah[ci*4+ji];
        __syncthreads();

        // ---- prediction / rec_loss accumulation (hs[t] vs x[b,t,c], t>=1) ----
        if (tid < 64 && t >= 1) {
            float p = pb;
            #pragma unroll 8
            for (int h = 0; h < 64; h++) p = fmaf(s[OFF_H + tid * 65 + h], s[OFF_PW + h], p);
            float dd = p - s[OFF_XT + tid];
            errsum = fmaf(dd, dd, errsum);
        }
        __syncthreads();
    }

    // ---- DNC output ----
    for (int i = tid; i < 4096; i += 256)
        out[DNC_OFF + (size_t)b * 4096 + i] = s[OFF_DNC + i] * (1.f / 256.f);

    // ---- rec_loss partial ----
    #pragma unroll
    for (int o = 16; o > 0; o >>= 1) errsum += __shfl_xor_sync(0xffffffffu, errsum, o);
    __syncthreads();
    if ((tid & 31) == 0) s[OFF_RED + (tid >> 5)] = errsum;
    __syncthreads();
    if (tid == 0) {
        float totv = 0.f;
        #pragma unroll
        for (int w = 0; w < 8; w++) totv += s[OFF_RED + w];
        g_rl[b] = totv;
    }
}

// ============================================================================
// Tiled fp32 NT GEMM: C[m][n] = act(sum_k A[m][k]*B[n][k] + bias[n])
// BM=BN=128, BK=16, 256 threads, 8x8 per thread.
// ============================================================================
template <bool RELU>
__global__ __launch_bounds__(256) void gemm_nt(
    const float* __restrict__ A, const float* __restrict__ Bm,
    const float* __restrict__ bias, float* __restrict__ Cm,
    int M, int N, int K)
{
    __shared__ __align__(16) float As[16 * 132];
    __shared__ __align__(16) float Bs[16 * 132];
    const int tid = threadIdx.x;
    const int tx = tid & 15, ty = tid >> 4;
    const int m_blk = blockIdx.y * 128, n_blk = blockIdx.x * 128;
    const int kq = tid & 3;          // 0..3  (k quad)
    const int row0 = tid >> 2;       // 0..63

    float acc[8][8];
    #pragma unroll
    for (int i = 0; i < 8; i++)
        #pragma unroll
        for (int j = 0; j < 8; j++) acc[i][j] = 0.f;

    for (int kt = 0; kt < K; kt += 16) {
        #pragma unroll
        for (int i = 0; i < 2; i++) {
            int r = row0 + i * 64;
            float4 av = *(const float4*)&A[(size_t)(m_blk + r) * K + kt + kq * 4];
            As[(kq * 4 + 0) * 132 + r] = av.x;
            As[(kq * 4 + 1) * 132 + r] = av.y;
            As[(kq * 4 + 2) * 132 + r] = av.z;
            As[(kq * 4 + 3) * 132 + r] = av.w;
            float4 bv = *(const float4*)&Bm[(size_t)(n_blk + r) * K + kt + kq * 4];
            Bs[(kq * 4 + 0) * 132 + r] = bv.x;
            Bs[(kq * 4 + 1) * 132 + r] = bv.y;
            Bs[(kq * 4 + 2) * 132 + r] = bv.z;
            Bs[(kq * 4 + 3) * 132 + r] = bv.w;
        }
        __syncthreads();
        #pragma unroll
        for (int kk = 0; kk < 16; kk++) {
            float4 a0 = *(const float4*)&As[kk * 132 + ty * 8];
            float4 a1 = *(const float4*)&As[kk * 132 + ty * 8 + 4];
            float4 b0 = *(const float4*)&Bs[kk * 132 + tx * 8];
            float4 b1 = *(const float4*)&Bs[kk * 132 + tx * 8 + 4];
            float a[8] = {a0.x, a0.y, a0.z, a0.w, a1.x, a1.y, a1.z, a1.w};
            float bb[8] = {b0.x, b0.y, b0.z, b0.w, b1.x, b1.y, b1.z, b1.w};
            #pragma unroll
            for (int i = 0; i < 8; i++)
                #pragma unroll
                for (int j = 0; j < 8; j++)
                    acc[i][j] = fmaf(a[i], bb[j], acc[i][j]);
        }
        __syncthreads();
    }

    #pragma unroll
    for (int i = 0; i < 8; i++) {
        int m = m_blk + ty * 8 + i;
        #pragma unroll
        for (int j = 0; j < 8; j += 4) {
            int n = n_blk + tx * 8 + j;
            float4 v;
            v.x = acc[i][j + 0] + bias[n + 0];
            v.y = acc[i][j + 1] + bias[n + 1];
            v.z = acc[i][j + 2] + bias[n + 2];
            v.w = acc[i][j + 3] + bias[n + 3];
            if (RELU) {
                v.x = fmaxf(v.x, 0.f); v.y = fmaxf(v.y, 0.f);
                v.z = fmaxf(v.z, 0.f); v.w = fmaxf(v.w, 0.f);
            }
            *(float4*)&Cm[(size_t)m * N + n] = v;
        }
    }
}

// ============================================================================
// logits[b,o] = mean_t (h2[b,t,:] @ clf3_w[o,:]) + clf3_b[o]
// ============================================================================
__global__ __launch_bounds__(256) void logits_kernel(
    const float* __restrict__ w3, const float* __restrict__ b3,
    float* __restrict__ out)
{
    __shared__ float red[16];
    const int b = blockIdx.x, tid = threadIdx.x;
    const float* base = g_h2 + (size_t)b * 256 * 1024;
    float p0 = 0.f, p1 = 0.f;
    for (int i = tid; i < 256 * 1024; i += 256) {
        float v = base[i];
        int j = i & 1023;
        p0 = fmaf(v, w3[j], p0);
        p1 = fmaf(v, w3[1024 + j], p1);
    }
    #pragma unroll
    for (int o = 16; o > 0; o >>= 1) {
        p0 += __shfl_xor_sync(0xffffffffu, p0, o);
        p1 += __shfl_xor_sync(0xffffffffu, p1, o);
    }
    if ((tid & 31) == 0) { red[(tid >> 5) * 2] = p0; red[(tid >> 5) * 2 + 1] = p1; }
    __syncthreads();
    if (tid == 0) {
        float s0 = 0.f, s1 = 0.f;
        #pragma unroll
        for (int w = 0; w < 8; w++) { s0 += red[w * 2]; s1 += red[w * 2 + 1]; }
        out[(size_t)b * 2 + 0] = s0 * (1.f / 256.f) + b3[0];
        out[(size_t)b * 2 + 1] = s1 * (1.f / 256.f) + b3[1];
    }
}

__global__ void finalize_kernel(float* __restrict__ out)
{
    if (threadIdx.x == 0) {
        float ss = 0.f;
        #pragma unroll
        for (int i = 0; i < BB; i++) ss += g_rl[i];
        out[RL_OFF] = ss / (32.f * 255.f * 64.f);
    }
}

// ============================================================================
extern "C" void kernel_launch(void* const* d_in, const int* in_sizes, int n_in,
                              void* d_out, int out_size)
{
    const float* x      = (const float*)d_in[0];
    const float* emb_w  = (const float*)d_in[1];
    const float* emb_b  = (const float*)d_in[2];
    const float* w_ih   = (const float*)d_in[3];
    const float* w_hh   = (const float*)d_in[4];
    const float* b_ih   = (const float*)d_in[5];
    const float* b_hh   = (const float*)d_in[6];
    const float* q_w    = (const float*)d_in[7];
    const float* q_b    = (const float*)d_in[8];
    const float* k_w    = (const float*)d_in[9];
    const float* k_b    = (const float*)d_in[10];
    const float* gate_b = (const float*)d_in[11];
    const float* pred_w = (const float*)d_in[12];
    const float* pred_b = (const float*)d_in[13];
    const float* clf1_w = (const float*)d_in[14];
    const float* clf1_b = (const float*)d_in[15];
    const float* clf2_w = (const float*)d_in[16];
    const float* clf2_b = (const float*)d_in[17];
    const float* clf3_w = (const float*)d_in[18];
    const float* clf3_b = (const float*)d_in[19];
    float* out = (float*)d_out;

    float *h1p = nullptr, *h2p = nullptr;
    cudaGetSymbolAddress((void**)&h1p, g_h1);
    cudaGetSymbolAddress((void**)&h2p, g_h2);

    cudaFuncSetAttribute(recurrent_kernel,
                         cudaFuncAttributeMaxDynamicSharedMemorySize, SMEM_BYTES);

    recurrent_kernel<<<BB, 256, SMEM_BYTES>>>(
        x, emb_w, emb_b, w_ih, w_hh, b_ih, b_hh,
        q_w, q_b, k_w, k_b, gate_b, pred_w, pred_b, out);

    // classifier layer 1: [8192,4096] x [2048,4096]^T -> relu
    dim3 g1(2048 / 128, 8192 / 128);
    gemm_nt<true><<<g1, 256>>>(out + MIX_OFF, clf1_w, clf1_b, h1p, 8192, 2048, 4096);

    // classifier layer 2: [8192,2048] x [1024,2048]^T -> relu
    dim3 g2(1024 / 128, 8192 / 128);
    gemm_nt<true><<<g2, 256>>>(h1p, clf2_w, clf2_b, h2p, 8192, 1024, 2048);

    logits_kernel<<<BB, 256>>>(clf3_w, clf3_b, out);
    finalize_kernel<<<1, 32>>>(out);
}